// round 3
// baseline (speedup 1.0000x reference)
#include <cuda_runtime.h>
#include <cuda_fp16.h>
#include <math.h>

// Problem constants
#define Bb   128
#define Nn   96
#define Dd   128
#define Mm   8192
#define KSEL 48
#define MT   128
#define NTILES (Mm / MT)          // 64
#define MSPLIT 8                  // K2 M-parallelism
#define TPS   (NTILES / MSPLIT)   // tiles per split = 8
#define SCALEF 0.08838834764831845f  // 1/sqrt(128)

// Scratch (static device globals -- allocation-free per harness rules)
__device__ __half g_S[(size_t)Bb * Nn * Mm];          // s logits, fp16 (201 MB)
__device__ float  g_part[(size_t)Bb * Nn * NTILES];   // per-(b,n,tile) partial sum exp(s)
__device__ float  g_O[(size_t)Bb * MSPLIT * Nn * Dd]; // partial attn outputs (50 MB)

#define SM_QP  97    // Qs row pad (k-major [128][97])
#define SM_TP  136   // K1 T tile pad (k-major [128][136]) -- 136*4B % 32B == 0 for v2.b64
#define SM_XP  97    // K2 x/p tile pad (m-major [128][97])
#define SM_T2P 132   // K2 T tile pad (m-major [128][132]) -- 132*4B % 16B == 0

// ---- packed f32x2 helpers (sm_100+) ----
typedef unsigned long long u64t;
__device__ __forceinline__ u64t pk2(float a, float b) {
    u64t r; asm("mov.b64 %0, {%1, %2};" : "=l"(r) : "f"(a), "f"(b)); return r;
}
__device__ __forceinline__ u64t bcast2(float a) {
    u64t r; asm("mov.b64 %0, {%1, %1};" : "=l"(r) : "f"(a)); return r;
}
__device__ __forceinline__ void upk2(u64t v, float& lo, float& hi) {
    asm("mov.b64 {%0, %1}, %2;" : "=f"(lo), "=f"(hi) : "l"(v));
}
#define FMA2(acc, a, b) asm("fma.rn.f32x2 %0, %1, %2, %0;" : "+l"(acc) : "l"(a), "l"(b))

// ---------------------------------------------------------------------------
// K1: S = Q @ T^T * scale  (per-(tile,b) 96x128 tile), fp16 S + exp partials
// ---------------------------------------------------------------------------
__global__ __launch_bounds__(256) void tlp_k1(const float* __restrict__ logits,
                                              const float* __restrict__ tl) {
    extern __shared__ float sm[];
    float* Qs = sm;                        // [128][SM_QP]  (k-major: Qs[k][n])
    float* Ts = sm + 128 * SM_QP;          // [128][SM_TP]  (k-major: Ts[k][m])

    const int b    = blockIdx.y;
    const int tile = blockIdx.x;
    const int tid  = threadIdx.x;
    const int tx   = tid & 15;
    const int ty   = tid >> 4;

    const float* qb = logits + (size_t)b * (Nn * Dd);
    for (int e = tid; e < Nn * Dd; e += 256) {
        int n = e >> 7, k = e & 127;
        Qs[k * SM_QP + n] = qb[e];
    }
    const float* tb = tl + (size_t)tile * MT * Dd;
    for (int e = tid; e < MT * Dd; e += 256) {
        int mm = e >> 7, k = e & 127;
        Ts[k * SM_TP + mm] = tb[e];
    }
    __syncthreads();

    u64t acc2[6][4];
#pragma unroll
    for (int i = 0; i < 6; i++)
#pragma unroll
        for (int j = 0; j < 4; j++) acc2[i][j] = 0ull;

    const int sty = 6 * ty;
    const int stx = 8 * ((tx + 2 * ty) & 15);   // bank-quad swizzle

#pragma unroll 4
    for (int k = 0; k < 128; k++) {
        u64t a2[6];
#pragma unroll
        for (int i = 0; i < 6; i++) a2[i] = bcast2(Qs[k * SM_QP + sty + i]);
        const u64t* brow = (const u64t*)(Ts + k * SM_TP + stx);  // 32B-aligned
        ulonglong2 b01 = *(const ulonglong2*)(brow);
        ulonglong2 b23 = *(const ulonglong2*)(brow + 2);
        u64t bp[4] = {b01.x, b01.y, b23.x, b23.y};
#pragma unroll
        for (int i = 0; i < 6; i++)
#pragma unroll
            for (int j = 0; j < 4; j++)
                FMA2(acc2[i][j], a2[i], bp[j]);
    }

    // Epilogue: scale, fp16 S, exp partial rowsums
    __half* So = g_S + (size_t)(b * Nn) * Mm + (size_t)tile * MT;
#pragma unroll
    for (int i = 0; i < 6; i++) {
        union { __half h[8]; uint4 u; } pk;
        float es = 0.f;
#pragma unroll
        for (int j = 0; j < 4; j++) {
            float lo, hi; upk2(acc2[i][j], lo, hi);
            float s0 = lo * SCALEF, s1 = hi * SCALEF;
            __half h0 = __float2half(s0), h1 = __float2half(s1);
            pk.h[2 * j] = h0; pk.h[2 * j + 1] = h1;
            es += __expf(__half2float(h0)) + __expf(__half2float(h1));
        }
        const int n = sty + i;
        *(uint4*)(So + (size_t)n * Mm + stx) = pk.u;
#pragma unroll
        for (int off = 8; off > 0; off >>= 1)
            es += __shfl_down_sync(0xffffffffu, es, off, 16);
        if (tx == 0)
            g_part[((size_t)b * Nn + n) * NTILES + tile] = es;
    }
}

// ---------------------------------------------------------------------------
// K2: grid (MSPLIT, B). Each CTA: TPS tiles of {threshold-48-of-96, masked exp,
//     partial O += P^T @ T}. Writes partial O to g_O.
// ---------------------------------------------------------------------------
__global__ __launch_bounds__(256) void tlp_k2(const float* __restrict__ tl) {
    extern __shared__ float sm[];
    float* Xt  = sm;                         // [128][SM_XP]   x then p (m-major)
    float* Ts  = sm + 128 * SM_XP;           // [128][SM_T2P]  T tile (m-major)
    float* Ls  = Ts + 128 * SM_T2P;          // [96]  log rowsum
    float* Thr = Ls + Nn;                    // [128] per-column thresholds

    const int split = blockIdx.x;
    const int b     = blockIdx.y;
    const int tid   = threadIdx.x;
    const int w     = tid >> 5;
    const int lane  = tid & 31;

    // Reduce K1 partials -> L[n] = log(rowsum)
    if (tid < Nn) {
        const float* pp = g_part + ((size_t)b * Nn + tid) * NTILES;
        float s = 0.f;
#pragma unroll
        for (int t = 0; t < NTILES; t++) s += pp[t];
        Ls[tid] = logf(s);
    }
    __syncthreads();

    u64t acc2[3][8];
#pragma unroll
    for (int r = 0; r < 3; r++)
#pragma unroll
        for (int c = 0; c < 8; c++) acc2[r][c] = 0ull;

    const int rn = 3 * lane;   // lane owns rows n = rn..rn+2
    const int cd = 16 * w;     // warp owns d-range [cd, cd+16)

    const __half* Sb = g_S + (size_t)(b * Nn) * Mm;
    const int tile0 = split * TPS;

    for (int tile = tile0; tile < tile0 + TPS; tile++) {
        // Load s tile transposed: Xt[m][n] = s - L[n]
        const __half* sp = Sb + (size_t)tile * MT;
        for (int e = tid; e < Nn * MT; e += 256) {
            int n = e >> 7, mm = e & 127;
            Xt[mm * SM_XP + n] = __half2float(sp[(size_t)n * Mm + mm]) - Ls[n];
        }
        const float* tb = tl + (size_t)tile * MT * Dd;
        for (int e = tid; e < MT * Dd; e += 256) {
            int mm = e >> 7, d = e & 127;
            Ts[mm * SM_T2P + d] = tb[e];
        }
        __syncthreads();

        // Per-column threshold: warp per column, 96 values in 3 regs/lane
        for (int c = 0; c < 16; c++) {
            const int mm = w * 16 + c;
            const float* col = Xt + mm * SM_XP;
            float v0 = col[lane], v1 = col[lane + 32], v2 = col[lane + 64];
            float s1 = v0 + v1 + v2;
            float s2 = v0 * v0 + v1 * v1 + v2 * v2;
            float mn = fminf(v0, fminf(v1, v2));
            float mx = fmaxf(v0, fmaxf(v1, v2));
#pragma unroll
            for (int off = 16; off > 0; off >>= 1) {
                s1 += __shfl_xor_sync(0xffffffffu, s1, off);
                s2 += __shfl_xor_sync(0xffffffffu, s2, off);
                mn = fminf(mn, __shfl_xor_sync(0xffffffffu, mn, off));
                mx = fmaxf(mx, __shfl_xor_sync(0xffffffffu, mx, off));
            }
            float mu  = s1 * (1.f / 96.f);
            float sig = sqrtf(fmaxf(s2 * (1.f / 96.f) - mu * mu, 1e-24f));
            float lo = mn, hi = mx, t = mu;   // 48th of 96 ~ median ~ mu
#pragma unroll 1
            for (int it = 0; it < 10; it++) {
                int cnt = __popc(__ballot_sync(0xffffffffu, v0 >= t))
                        + __popc(__ballot_sync(0xffffffffu, v1 >= t))
                        + __popc(__ballot_sync(0xffffffffu, v2 >= t));
                if (cnt >= KSEL) { lo = t; if (cnt == KSEL) break; }
                else hi = t;
                float tn = t + (float)(cnt - KSEL) * sig * 0.02611f;
                if (!(tn > lo && tn < hi)) tn = 0.5f * (lo + hi);
                t = tn;
            }
            if (lane == 0) Thr[mm] = lo;
        }
        __syncthreads();

        // Masked exp in place
        {
            const int mm = tid >> 1;
            const int nh = (tid & 1) * 48;
            const float th = Thr[mm];
            float* col = Xt + mm * SM_XP + nh;
#pragma unroll
            for (int i = 0; i < 48; i++) {
                float x = col[i];
                col[i] = (x >= th) ? __expf(x) : 0.f;
            }
        }
        __syncthreads();

        // O[n][d] += sum_m p[m][n] * T[m][d]   (packed f32x2 over d-pairs)
#pragma unroll 2
        for (int mm = 0; mm < MT; mm++) {
            u64t p0 = bcast2(Xt[mm * SM_XP + rn]);
            u64t p1 = bcast2(Xt[mm * SM_XP + rn + 1]);
            u64t p2 = bcast2(Xt[mm * SM_XP + rn + 2]);
            const u64t* trow = (const u64t*)(Ts + mm * SM_T2P + cd);  // 16B-aligned
            ulonglong2 t01 = *(const ulonglong2*)(trow);
            ulonglong2 t23 = *(const ulonglong2*)(trow + 2);
            ulonglong2 t45 = *(const ulonglong2*)(trow + 4);
            ulonglong2 t67 = *(const ulonglong2*)(trow + 6);
            u64t tp[8] = {t01.x, t01.y, t23.x, t23.y, t45.x, t45.y, t67.x, t67.y};
#pragma unroll
            for (int c = 0; c < 8; c++) {
                FMA2(acc2[0][c], p0, tp[c]);
                FMA2(acc2[1][c], p1, tp[c]);
                FMA2(acc2[2][c], p2, tp[c]);
            }
        }
        __syncthreads();
    }

    // Write partial O
    float* ob = g_O + (((size_t)b * MSPLIT + split) * Nn) * Dd;
#pragma unroll
    for (int r = 0; r < 3; r++) {
        float v[16];
#pragma unroll
        for (int c = 0; c < 8; c++) upk2(acc2[r][c], v[2 * c], v[2 * c + 1]);
        float* dst = ob + (size_t)(rn + r) * Dd + cd;
#pragma unroll
        for (int c = 0; c < 4; c++)
            *(float4*)(dst + 4 * c) = make_float4(v[4 * c], v[4 * c + 1],
                                                  v[4 * c + 2], v[4 * c + 3]);
    }
}

// ---------------------------------------------------------------------------
// K3: out = q + sum_splits g_O
// ---------------------------------------------------------------------------
__global__ __launch_bounds__(256) void tlp_k3(const float* __restrict__ logits,
                                              float* __restrict__ out) {
    const size_t i4 = (size_t)blockIdx.x * 256 + threadIdx.x;   // float4 index
    const size_t nf4 = (size_t)Bb * Nn * Dd / 4;                // 393216
    if (i4 >= nf4) return;
    const size_t b   = i4 / (Nn * Dd / 4);
    const size_t rem = i4 % (Nn * Dd / 4);

    float4 acc = ((const float4*)logits)[i4];
    const float4* po = (const float4*)g_O + (b * MSPLIT) * (Nn * Dd / 4) + rem;
#pragma unroll
    for (int s = 0; s < MSPLIT; s++) {
        float4 v = po[(size_t)s * (Nn * Dd / 4)];
        acc.x += v.x; acc.y += v.y; acc.z += v.z; acc.w += v.w;
    }
    ((float4*)out)[i4] = acc;
}

extern "C" void kernel_launch(void* const* d_in, const int* in_sizes, int n_in,
                              void* d_out, int out_size) {
    const float* logits = (const float*)d_in[0];
    const float* tl     = (const float*)d_in[1];
    float* out          = (float*)d_out;

    const int smem1 = (128 * SM_QP + 128 * SM_TP) * 4;               // 119296 B
    const int smem2 = (128 * SM_XP + 128 * SM_T2P + Nn + 128) * 4;   // 118144 B

    cudaFuncSetAttribute(tlp_k1, cudaFuncAttributeMaxDynamicSharedMemorySize, smem1);
    cudaFuncSetAttribute(tlp_k2, cudaFuncAttributeMaxDynamicSharedMemorySize, smem2);

    tlp_k1<<<dim3(NTILES, Bb), 256, smem1>>>(logits, tl);
    tlp_k2<<<dim3(MSPLIT, Bb), 256, smem2>>>(tl);
    tlp_k3<<<(Bb * Nn * Dd / 4 + 255) / 256, 256>>>(logits, out);
}

// round 5
// speedup vs baseline: 2.3896x; 2.3896x over previous
#include <cuda_runtime.h>
#include <cuda_fp16.h>
#include <cuda_bf16.h>
#include <stdint.h>
#include <math.h>

// Problem constants
#define Bb   128
#define Nn   96
#define Dd   128
#define Mm   8192
#define KSEL 48
#define MT   128
#define NTILES (Mm / MT)          // 64
#define MSPLIT 8
#define TPS   (NTILES / MSPLIT)   // 8
#define SCALEF 0.08838834764831845f  // 1/sqrt(128)

// Scratch (static device globals -- allocation-free per harness rules)
__device__ __half g_S[(size_t)Bb * Nn * Mm];          // fp16 logits (201 MB)
__device__ float  g_part[(size_t)Bb * Nn * NTILES];   // partial sum exp(s)
__device__ float  g_O[(size_t)Bb * MSPLIT * Nn * Dd]; // partial attn outputs

#define PB   136   // bf16 operand pitch (32b pitch 68 -> conflict-free frag loads)
#define SM_XP 97   // K2 x tile pad (m-major [128][97])

__device__ __forceinline__ void mma_bf16(float* c,
                                         uint32_t a0, uint32_t a1, uint32_t a2, uint32_t a3,
                                         uint32_t b0, uint32_t b1) {
    asm volatile(
        "mma.sync.aligned.m16n8k16.row.col.f32.bf16.bf16.f32 "
        "{%0,%1,%2,%3},{%4,%5,%6,%7},{%8,%9},{%0,%1,%2,%3};"
        : "+f"(c[0]), "+f"(c[1]), "+f"(c[2]), "+f"(c[3])
        : "r"(a0), "r"(a1), "r"(a2), "r"(a3), "r"(b0), "r"(b1));
}

__device__ __forceinline__ __nv_bfloat162 tobf2(float2 v) {
    return __nv_bfloat162{__float2bfloat16(v.x), __float2bfloat16(v.y)};
}

// ---------------------------------------------------------------------------
// K1: S = Q @ T^T * scale via bf16 HMMA. fp16 S to gmem + exp rowsum partials.
// grid (NTILES, B), 256 threads. Warp w owns output cols m in [16w,16w+16).
// ---------------------------------------------------------------------------
__global__ __launch_bounds__(256) void tlp_k1(const float* __restrict__ logits,
                                              const float* __restrict__ tl) {
    extern __shared__ char smraw[];
    __nv_bfloat16* Qs = (__nv_bfloat16*)smraw;   // [96][PB]   A: Q[n][k]
    __nv_bfloat16* Ts = Qs + Nn * PB;            // [128][PB]  B: T[m][k] (col-major B)
    float*         Rs = (float*)(Ts + MT * PB);  // [96] rowsums

    const int b = blockIdx.y, tile = blockIdx.x, tid = threadIdx.x;
    const int w = tid >> 5, lane = tid & 31, g = lane >> 2, q = lane & 3;

    if (tid < Nn) Rs[tid] = 0.f;

    const float2* q2 = (const float2*)(logits + (size_t)b * Nn * Dd);
    for (int e = tid; e < Nn * Dd / 2; e += 256) {
        int n = e >> 6, kk = e & 63;
        ((__nv_bfloat162*)(Qs + n * PB))[kk] = tobf2(q2[e]);
    }
    const float2* t2 = (const float2*)(tl + (size_t)tile * MT * Dd);
    for (int e = tid; e < MT * Dd / 2; e += 256) {
        int mm = e >> 6, kk = e & 63;
        ((__nv_bfloat162*)(Ts + mm * PB))[kk] = tobf2(t2[e]);
    }
    __syncthreads();

    const uint32_t* Q32 = (const uint32_t*)Qs;
    const uint32_t* T32 = (const uint32_t*)Ts;

    float acc[6][2][4];
#pragma unroll
    for (int i = 0; i < 6; i++)
#pragma unroll
        for (int j = 0; j < 2; j++)
#pragma unroll
            for (int c = 0; c < 4; c++) acc[i][j][c] = 0.f;

#pragma unroll
    for (int ko = 0; ko < 8; ko++) {
        uint32_t bf[2][2];
#pragma unroll
        for (int j = 0; j < 2; j++) {
            int cm = 16 * w + 8 * j + g;
            bf[j][0] = T32[cm * 68 + ko * 8 + q];
            bf[j][1] = T32[cm * 68 + ko * 8 + 4 + q];
        }
#pragma unroll
        for (int i = 0; i < 6; i++) {
            int r = 16 * i + g;
            uint32_t a0 = Q32[r * 68 + ko * 8 + q];
            uint32_t a1 = Q32[(r + 8) * 68 + ko * 8 + q];
            uint32_t a2 = Q32[r * 68 + ko * 8 + 4 + q];
            uint32_t a3 = Q32[(r + 8) * 68 + ko * 8 + 4 + q];
            mma_bf16(acc[i][0], a0, a1, a2, a3, bf[0][0], bf[0][1]);
            mma_bf16(acc[i][1], a0, a1, a2, a3, bf[1][0], bf[1][1]);
        }
    }

    // Epilogue: scale, fp16 store, exp rowsum partials (exp of quantized value)
    __half* So = g_S + (size_t)(b * Nn) * Mm + (size_t)tile * MT;
#pragma unroll
    for (int i = 0; i < 6; i++) {
        const int r = 16 * i + g;
        float elo = 0.f, ehi = 0.f;
#pragma unroll
        for (int j = 0; j < 2; j++) {
            const int mloc = 16 * w + 8 * j + 2 * q;
            float* cf = acc[i][j];
            __half h0 = __float2half(cf[0] * SCALEF);
            __half h1 = __float2half(cf[1] * SCALEF);
            *(__half2*)(So + (size_t)r * Mm + mloc) = __halves2half2(h0, h1);
            elo += __expf(__half2float(h0)) + __expf(__half2float(h1));
            __half h2 = __float2half(cf[2] * SCALEF);
            __half h3 = __float2half(cf[3] * SCALEF);
            *(__half2*)(So + (size_t)(r + 8) * Mm + mloc) = __halves2half2(h2, h3);
            ehi += __expf(__half2float(h2)) + __expf(__half2float(h3));
        }
        elo += __shfl_xor_sync(0xffffffffu, elo, 1);
        elo += __shfl_xor_sync(0xffffffffu, elo, 2);
        ehi += __shfl_xor_sync(0xffffffffu, ehi, 1);
        ehi += __shfl_xor_sync(0xffffffffu, ehi, 2);
        if (q == 0) {
            atomicAdd(&Rs[r], elo);
            atomicAdd(&Rs[r + 8], ehi);
        }
    }
    __syncthreads();
    if (tid < Nn)
        g_part[((size_t)b * Nn + tid) * NTILES + tile] = Rs[tid];
}

// ---------------------------------------------------------------------------
// K2: grid (MSPLIT, B). Per tile: threshold 48-of-96, masked exp -> Pb (bf16,
// [n][m]), T transposed -> Td (bf16, [d][m]), O += P @ T via HMMA.
// ---------------------------------------------------------------------------
__global__ __launch_bounds__(256) void tlp_k2(const float* __restrict__ tl) {
    extern __shared__ char smraw[];
    float*         Xt  = (float*)smraw;                       // [128][SM_XP]
    __nv_bfloat16* Pb  = (__nv_bfloat16*)(Xt + 128 * SM_XP);  // [96][PB]  A: P[n][m]
    __nv_bfloat16* Td  = Pb + Nn * PB;                        // [128][PB] B: T^T[d][m]
    float*         Ls  = (float*)(Td + MT * PB);              // [96]
    float*         Thr = Ls + Nn;                             // [128]

    const int split = blockIdx.x, b = blockIdx.y, tid = threadIdx.x;
    const int w = tid >> 5, lane = tid & 31, g = lane >> 2, q = lane & 3;

    if (tid < Nn) {
        const float* pp = g_part + ((size_t)b * Nn + tid) * NTILES;
        float s = 0.f;
#pragma unroll
        for (int t = 0; t < NTILES; t++) s += pp[t];
        Ls[tid] = logf(s);
    }
    __syncthreads();

    float acc[6][2][4];
#pragma unroll
    for (int i = 0; i < 6; i++)
#pragma unroll
        for (int j = 0; j < 2; j++)
#pragma unroll
            for (int c = 0; c < 4; c++) acc[i][j][c] = 0.f;

    const __half* Sb = g_S + (size_t)(b * Nn) * Mm;
    const int tile0 = split * TPS;

    for (int tile = tile0; tile < tile0 + TPS; tile++) {
        // Load s tile transposed: Xt[m][n] = s - L[n]
        const __half* sp = Sb + (size_t)tile * MT;
        for (int e = tid; e < Nn * MT; e += 256) {
            int n = e >> 7, mm = e & 127;
            Xt[mm * SM_XP + n] = __half2float(sp[(size_t)n * Mm + mm]) - Ls[n];
        }
        // Load T tile transposed to [d][m] bf16
        const float* tb = tl + (size_t)tile * MT * Dd;
        for (int e = tid; e < MT * Dd; e += 256) {
            int mm = e >> 7, d = e & 127;
            Td[d * PB + mm] = __float2bfloat16(tb[e]);
        }
        __syncthreads();

        // Per-column threshold: warp per column m, 96 n-values in 3 regs/lane
        for (int c = 0; c < 16; c++) {
            const int mm = w * 16 + c;
            const float* col = Xt + mm * SM_XP;
            float v0 = col[lane], v1 = col[lane + 32], v2 = col[lane + 64];
            float s1 = v0 + v1 + v2;
            float s2 = v0 * v0 + v1 * v1 + v2 * v2;
            float mn = fminf(v0, fminf(v1, v2));
            float mx = fmaxf(v0, fmaxf(v1, v2));
#pragma unroll
            for (int off = 16; off > 0; off >>= 1) {
                s1 += __shfl_xor_sync(0xffffffffu, s1, off);
                s2 += __shfl_xor_sync(0xffffffffu, s2, off);
                mn = fminf(mn, __shfl_xor_sync(0xffffffffu, mn, off));
                mx = fmaxf(mx, __shfl_xor_sync(0xffffffffu, mx, off));
            }
            float mu  = s1 * (1.f / 96.f);
            float sig = sqrtf(fmaxf(s2 * (1.f / 96.f) - mu * mu, 1e-24f));
            float lo = mn, hi = mx, t = mu;
#pragma unroll 1
            for (int it = 0; it < 12; it++) {
                int cnt = __popc(__ballot_sync(0xffffffffu, v0 >= t))
                        + __popc(__ballot_sync(0xffffffffu, v1 >= t))
                        + __popc(__ballot_sync(0xffffffffu, v2 >= t));
                if (cnt >= KSEL) { lo = t; if (cnt == KSEL) break; }
                else hi = t;
                float tn = t + (float)(cnt - KSEL) * sig * 0.02611f;
                if (!(tn > lo && tn < hi)) tn = 0.5f * (lo + hi);
                t = tn;
            }
            if (lane == 0) Thr[mm] = lo;
        }
        __syncthreads();

        // Masked exp, transposed write: Pb[n][m] = (x>=th) ? exp(x) : 0  (bf16)
        {
            const int mm = tid >> 1;
            const int nh = (tid & 1) * 48;
            const float th = Thr[mm];
            const float* col = Xt + mm * SM_XP + nh;
#pragma unroll
            for (int i = 0; i < 48; i++) {
                float x = col[i];
                float p = (x >= th) ? __expf(x) : 0.f;
                Pb[(nh + i) * PB + mm] = __float2bfloat16(p);
            }
        }
        __syncthreads();

        // O[n][d] += P[n][m] @ T[m][d]  (HMMA, k = m, 8 ksteps)
        const uint32_t* P32 = (const uint32_t*)Pb;
        const uint32_t* D32 = (const uint32_t*)Td;
#pragma unroll
        for (int ko = 0; ko < 8; ko++) {
            uint32_t bf[2][2];
#pragma unroll
            for (int j = 0; j < 2; j++) {
                int cd = 16 * w + 8 * j + g;
                bf[j][0] = D32[cd * 68 + ko * 8 + q];
                bf[j][1] = D32[cd * 68 + ko * 8 + 4 + q];
            }
#pragma unroll
            for (int i = 0; i < 6; i++) {
                int r = 16 * i + g;
                uint32_t a0 = P32[r * 68 + ko * 8 + q];
                uint32_t a1 = P32[(r + 8) * 68 + ko * 8 + q];
                uint32_t a2 = P32[r * 68 + ko * 8 + 4 + q];
                uint32_t a3 = P32[(r + 8) * 68 + ko * 8 + 4 + q];
                mma_bf16(acc[i][0], a0, a1, a2, a3, bf[0][0], bf[0][1]);
                mma_bf16(acc[i][1], a0, a1, a2, a3, bf[1][0], bf[1][1]);
            }
        }
        __syncthreads();   // protect smem before next tile overwrites
    }

    // Write partial O
    float* ob = g_O + (((size_t)b * MSPLIT + split) * Nn) * Dd;
#pragma unroll
    for (int i = 0; i < 6; i++) {
        const int r = 16 * i + g;
#pragma unroll
        for (int j = 0; j < 2; j++) {
            const int dloc = 16 * w + 8 * j + 2 * q;
            float* cf = acc[i][j];
            *(float2*)(ob + (size_t)r * Dd + dloc)       = make_float2(cf[0], cf[1]);
            *(float2*)(ob + (size_t)(r + 8) * Dd + dloc) = make_float2(cf[2], cf[3]);
        }
    }
}

// ---------------------------------------------------------------------------
// K3: out = q + sum_splits g_O
// ---------------------------------------------------------------------------
__global__ __launch_bounds__(256) void tlp_k3(const float* __restrict__ logits,
                                              float* __restrict__ out) {
    const size_t i4 = (size_t)blockIdx.x * 256 + threadIdx.x;
    const size_t nf4 = (size_t)Bb * Nn * Dd / 4;
    if (i4 >= nf4) return;
    const size_t b   = i4 / (Nn * Dd / 4);
    const size_t rem = i4 % (Nn * Dd / 4);

    float4 acc = ((const float4*)logits)[i4];
    const float4* po = (const float4*)g_O + (b * MSPLIT) * (Nn * Dd / 4) + rem;
#pragma unroll
    for (int s = 0; s < MSPLIT; s++) {
        float4 v = po[(size_t)s * (Nn * Dd / 4)];
        acc.x += v.x; acc.y += v.y; acc.z += v.z; acc.w += v.w;
    }
    ((float4*)out)[i4] = acc;
}

extern "C" void kernel_launch(void* const* d_in, const int* in_sizes, int n_in,
                              void* d_out, int out_size) {
    const float* logits = (const float*)d_in[0];
    const float* tl     = (const float*)d_in[1];
    float* out          = (float*)d_out;

    const int smem1 = (Nn * PB + MT * PB) * 2 + Nn * 4;                       // 61312 B
    const int smem2 = 128 * SM_XP * 4 + (Nn * PB + MT * PB) * 2 + (Nn + 128) * 4; // 111488 B

    cudaFuncSetAttribute(tlp_k1, cudaFuncAttributeMaxDynamicSharedMemorySize, smem1);
    cudaFuncSetAttribute(tlp_k2, cudaFuncAttributeMaxDynamicSharedMemorySize, smem2);

    tlp_k1<<<dim3(NTILES, Bb), 256, smem1>>>(logits, tl);
    tlp_k2<<<dim3(MSPLIT, Bb), 256, smem2>>>(tl);
    tlp_k3<<<(Bb * Nn * Dd / 4 + 255) / 256, 256>>>(logits, out);
}

// round 6
// speedup vs baseline: 3.6450x; 1.5254x over previous
#include <cuda_runtime.h>
#include <cuda_fp16.h>
#include <cuda_bf16.h>
#include <stdint.h>
#include <math.h>

// Problem constants
#define Bb   128
#define Nn   96
#define Dd   128
#define Mm   8192
#define KSEL 48
#define MT   128
#define NTILES (Mm / MT)          // 64
#define MSPLIT 8
#define TPS   (NTILES / MSPLIT)   // 8
#define SCALEF 0.08838834764831845f  // 1/sqrt(128)

// Scratch (static device globals -- allocation-free per harness rules)
__device__ __half g_S[(size_t)Bb * Nn * Mm];          // fp16 logits (201 MB)
__device__ float  g_part[(size_t)Bb * Nn * NTILES];   // partial sum exp(s)
__device__ float  g_O[(size_t)Bb * MSPLIT * Nn * Dd]; // partial attn outputs

#define PB 136   // bf16 pitch for Q/T tiles (272 B row: 16B-aligned, LDSM conflict-free)
#define XP 104   // half pitch for K2 s/P tile (208 B row: 16B-aligned, LDSM conflict-free)

__device__ __forceinline__ void mma_bf16(float* c,
                                         uint32_t a0, uint32_t a1, uint32_t a2, uint32_t a3,
                                         uint32_t b0, uint32_t b1) {
    asm volatile(
        "mma.sync.aligned.m16n8k16.row.col.f32.bf16.bf16.f32 "
        "{%0,%1,%2,%3},{%4,%5,%6,%7},{%8,%9},{%0,%1,%2,%3};"
        : "+f"(c[0]), "+f"(c[1]), "+f"(c[2]), "+f"(c[3])
        : "r"(a0), "r"(a1), "r"(a2), "r"(a3), "r"(b0), "r"(b1));
}

#define LDSM_X4(r0, r1, r2, r3, addr)                                        \
    asm volatile("ldmatrix.sync.aligned.m8n8.x4.shared.b16 {%0,%1,%2,%3}, [%4];" \
                 : "=r"(r0), "=r"(r1), "=r"(r2), "=r"(r3) : "r"(addr))

#define LDSM_X4_T(r0, r1, r2, r3, addr)                                      \
    asm volatile("ldmatrix.sync.aligned.m8n8.x4.trans.shared.b16 {%0,%1,%2,%3}, [%4];" \
                 : "=r"(r0), "=r"(r1), "=r"(r2), "=r"(r3) : "r"(addr))

__device__ __forceinline__ unsigned sptr(const void* p) {
    return (unsigned)__cvta_generic_to_shared(p);
}

__device__ __forceinline__ __nv_bfloat162 tobf2(float2 v) {
    return __nv_bfloat162{__float2bfloat16(v.x), __float2bfloat16(v.y)};
}

// ---------------------------------------------------------------------------
// K1: S = Q @ T^T * scale via bf16 HMMA + ldmatrix. fp16 S + exp rowsum partials.
// grid (NTILES, B), 256 threads. Warp w owns output cols m in [16w, 16w+16).
// ---------------------------------------------------------------------------
__global__ __launch_bounds__(256) void tlp_k1(const float* __restrict__ logits,
                                              const float* __restrict__ tl) {
    extern __shared__ char smraw[];
    __nv_bfloat16* Qs = (__nv_bfloat16*)smraw;   // [96][PB]   Q[n][k]
    __nv_bfloat16* Ts = Qs + Nn * PB;            // [128][PB]  T[m][k]
    float*         Rs = (float*)(Ts + MT * PB);  // [96] rowsums

    const int b = blockIdx.y, tile = blockIdx.x, tid = threadIdx.x;
    const int w = tid >> 5, lane = tid & 31, g = lane >> 2, q = lane & 3;

    if (tid < Nn) Rs[tid] = 0.f;

    const float2* q2 = (const float2*)(logits + (size_t)b * Nn * Dd);
    for (int e = tid; e < Nn * Dd / 2; e += 256) {
        int n = e >> 6, kk = e & 63;
        ((__nv_bfloat162*)(Qs + n * PB))[kk] = tobf2(q2[e]);
    }
    const float2* t2 = (const float2*)(tl + (size_t)tile * MT * Dd);
    for (int e = tid; e < MT * Dd / 2; e += 256) {
        int mm = e >> 6, kk = e & 63;
        ((__nv_bfloat162*)(Ts + mm * PB))[kk] = tobf2(t2[e]);
    }
    __syncthreads();

    float acc[6][2][4];
#pragma unroll
    for (int i = 0; i < 6; i++)
#pragma unroll
        for (int j = 0; j < 2; j++)
#pragma unroll
            for (int c = 0; c < 4; c++) acc[i][j][c] = 0.f;

    const unsigned qb32 = sptr(Qs), tb32 = sptr(Ts);
    const int lsub = lane & 7, grp = lane >> 3;
    // A (non-trans): lanes 0-15 -> rows, 16-31 -> rows with col+8
    const unsigned a_loff = ((unsigned)((lane & 15) * PB + (lane >> 4) * 8)) * 2;
    // B (non-trans, col-major B = T rows): grp0 row+0/col+0, grp1 row+0/col+8,
    //                                      grp2 row+8/col+0, grp3 row+8/col+8
    const unsigned b_loff =
        ((unsigned)((16 * w + ((grp & 2) ? 8 : 0) + lsub) * PB + ((grp & 1) ? 8 : 0))) * 2;

#pragma unroll
    for (int ko = 0; ko < 8; ko++) {
        uint32_t b0, b1, b2, b3;
        LDSM_X4(b0, b1, b2, b3, tb32 + ko * 32 + b_loff);   // ko*16 halves
#pragma unroll
        for (int i = 0; i < 6; i++) {
            uint32_t a0, a1, a2, a3;
            LDSM_X4(a0, a1, a2, a3, qb32 + (unsigned)(16 * i * PB) * 2 + ko * 32 + a_loff);
            mma_bf16(acc[i][0], a0, a1, a2, a3, b0, b1);
            mma_bf16(acc[i][1], a0, a1, a2, a3, b2, b3);
        }
    }

    // Epilogue: scale, fp16 store, exp rowsum partials (exp of quantized value)
    __half* So = g_S + (size_t)(b * Nn) * Mm + (size_t)tile * MT;
#pragma unroll
    for (int i = 0; i < 6; i++) {
        const int r = 16 * i + g;
        float elo = 0.f, ehi = 0.f;
#pragma unroll
        for (int j = 0; j < 2; j++) {
            const int mloc = 16 * w + 8 * j + 2 * q;
            float* cf = acc[i][j];
            __half h0 = __float2half(cf[0] * SCALEF);
            __half h1 = __float2half(cf[1] * SCALEF);
            *(__half2*)(So + (size_t)r * Mm + mloc) = __halves2half2(h0, h1);
            elo += __expf(__half2float(h0)) + __expf(__half2float(h1));
            __half h2 = __float2half(cf[2] * SCALEF);
            __half h3 = __float2half(cf[3] * SCALEF);
            *(__half2*)(So + (size_t)(r + 8) * Mm + mloc) = __halves2half2(h2, h3);
            ehi += __expf(__half2float(h2)) + __expf(__half2float(h3));
        }
        elo += __shfl_xor_sync(0xffffffffu, elo, 1);
        elo += __shfl_xor_sync(0xffffffffu, elo, 2);
        ehi += __shfl_xor_sync(0xffffffffu, ehi, 1);
        ehi += __shfl_xor_sync(0xffffffffu, ehi, 2);
        if (q == 0) {
            atomicAdd(&Rs[r], elo);
            atomicAdd(&Rs[r + 8], ehi);
        }
    }
    __syncthreads();
    if (tid < Nn)
        g_part[((size_t)b * Nn + tid) * NTILES + tile] = Rs[tid];
}

// ---------------------------------------------------------------------------
// K2: grid (MSPLIT, B). Per tile: s-tile fp16 [m][n] in smem, threshold 48-of-96
// per column m, masked exp written IN PLACE as bf16 P[m][n]; T kept [m][d] bf16;
// O += P^T @ T via HMMA with ldmatrix.trans operands. Partial O to g_O.
// ---------------------------------------------------------------------------
__global__ __launch_bounds__(256) void tlp_k2(const float* __restrict__ tl) {
    extern __shared__ char smraw[];
    __half*        Xs  = (__half*)smraw;                     // [128][XP] s, then P (bf16)
    __nv_bfloat16* Tt  = (__nv_bfloat16*)(smraw + 128 * XP * 2); // [128][PB] T[m][d]
    float*         Ls  = (float*)(smraw + 128 * XP * 2 + 128 * PB * 2); // [96]
    float*         Thr = Ls + Nn;                            // [128]

    const int split = blockIdx.x, b = blockIdx.y, tid = threadIdx.x;
    const int w = tid >> 5, lane = tid & 31, g = lane >> 2, q = lane & 3;

    if (tid < Nn) {
        const float* pp = g_part + ((size_t)b * Nn + tid) * NTILES;
        float s = 0.f;
#pragma unroll
        for (int t = 0; t < NTILES; t++) s += pp[t];
        Ls[tid] = logf(s);
    }
    __syncthreads();

    const float L0 = Ls[lane], L1 = Ls[lane + 32], L2 = Ls[lane + 64];

    float acc[6][2][4];
#pragma unroll
    for (int i = 0; i < 6; i++)
#pragma unroll
        for (int j = 0; j < 2; j++)
#pragma unroll
            for (int c = 0; c < 4; c++) acc[i][j][c] = 0.f;

    const unsigned xs32 = sptr(Xs), tt32 = sptr(Tt);
    const int lsub = lane & 7, grp = lane >> 3;
    // A = P^T via ldmatrix.trans on P[m][n]:
    //   grp0 row+0/col+0, grp1 row+0/col+8, grp2 row+8/col+0, grp3 row+8/col+8
    const unsigned a_loff =
        ((unsigned)((((grp & 2) ? 8 : 0) + lsub) * XP + ((grp & 1) ? 8 : 0))) * 2;
    // B = T^T via ldmatrix.trans on T[m][d]:
    //   grp0 row+0/col+0, grp1 row+8/col+0, grp2 row+0/col+8, grp3 row+8/col+8
    const unsigned b_loff =
        ((unsigned)((((grp & 1) ? 8 : 0) + lsub) * PB + 16 * w + ((grp & 2) ? 8 : 0))) * 2;

    const __half* Sb = g_S + (size_t)(b * Nn) * Mm;
    const int tile0 = split * TPS;

    for (int tile = tile0; tile < tile0 + TPS; tile++) {
        // Copy s tile transposed into fp16 [m][n]
        const __half* sp = Sb + (size_t)tile * MT;
        for (int e = tid; e < Nn * MT; e += 256) {
            int n = e >> 7, mm = e & 127;
            Xs[mm * XP + n] = sp[(size_t)n * Mm + mm];
        }
        // Copy T tile [m][d] as bf16 (coalesced, vectorized)
        const float2* tb2 = (const float2*)(tl + (size_t)tile * MT * Dd);
        for (int e = tid; e < MT * Dd / 2; e += 256) {
            int mm = e >> 6, d2 = e & 63;
            ((__nv_bfloat162*)(Tt + mm * PB))[d2] = tobf2(tb2[e]);
        }
        __syncthreads();

        // Per-column threshold: warp per column m, x = s - L[n], 3 regs/lane
        for (int c = 0; c < 16; c++) {
            const int mm = w * 16 + c;
            const __half* colh = Xs + mm * XP;
            float v0 = __half2float(colh[lane])      - L0;
            float v1 = __half2float(colh[lane + 32]) - L1;
            float v2 = __half2float(colh[lane + 64]) - L2;
            float s1 = v0 + v1 + v2;
            float s2 = v0 * v0 + v1 * v1 + v2 * v2;
            float mn = fminf(v0, fminf(v1, v2));
            float mx = fmaxf(v0, fmaxf(v1, v2));
#pragma unroll
            for (int off = 16; off > 0; off >>= 1) {
                s1 += __shfl_xor_sync(0xffffffffu, s1, off);
                s2 += __shfl_xor_sync(0xffffffffu, s2, off);
                mn = fminf(mn, __shfl_xor_sync(0xffffffffu, mn, off));
                mx = fmaxf(mx, __shfl_xor_sync(0xffffffffu, mx, off));
            }
            float mu  = s1 * (1.f / 96.f);
            float sig = sqrtf(fmaxf(s2 * (1.f / 96.f) - mu * mu, 1e-24f));
            float lo = mn, hi = mx, t = mu;
#pragma unroll 1
            for (int it = 0; it < 12; it++) {
                int cnt = __popc(__ballot_sync(0xffffffffu, v0 >= t))
                        + __popc(__ballot_sync(0xffffffffu, v1 >= t))
                        + __popc(__ballot_sync(0xffffffffu, v2 >= t));
                if (cnt >= KSEL) { lo = t; if (cnt == KSEL) break; }
                else hi = t;
                float tn = t + (float)(cnt - KSEL) * sig * 0.02611f;
                if (!(tn > lo && tn < hi)) tn = 0.5f * (lo + hi);
                t = tn;
            }
            if (lane == 0) Thr[mm] = lo;
        }
        __syncthreads();

        // Masked exp IN PLACE: P[m][n] (bf16) over the s halves. Each element is
        // read and overwritten by its owner thread only.
        {
            const int mm = tid >> 1;
            const int nh = (tid & 1) * 48;
            const float th = Thr[mm];
            __half* colp = Xs + mm * XP + nh;
            const float2* Lp = (const float2*)(Ls + nh);
#pragma unroll
            for (int i = 0; i < 24; i++) {
                __half2 hv = ((const __half2*)colp)[i];
                float2 Lv = Lp[i];
                float x0 = __half2float(hv.x) - Lv.x;
                float x1 = __half2float(hv.y) - Lv.y;
                float p0 = (x0 >= th) ? __expf(x0) : 0.f;
                float p1 = (x1 >= th) ? __expf(x1) : 0.f;
                ((__nv_bfloat162*)colp)[i] =
                    __nv_bfloat162{__float2bfloat16(p0), __float2bfloat16(p1)};
            }
        }
        __syncthreads();

        // O[n][d] += P^T[n][m] @ T[m][d]  (k = m, 8 ksteps, ldmatrix.trans)
#pragma unroll
        for (int ko = 0; ko < 8; ko++) {
            uint32_t b0, b1, b2, b3;
            LDSM_X4_T(b0, b1, b2, b3, tt32 + (unsigned)(ko * 16 * PB) * 2 + b_loff);
#pragma unroll
            for (int i = 0; i < 6; i++) {
                uint32_t a0, a1, a2, a3;
                LDSM_X4_T(a0, a1, a2, a3,
                          xs32 + (unsigned)(ko * 16 * XP) * 2 + a_loff + (unsigned)(16 * i) * 2);
                mma_bf16(acc[i][0], a0, a1, a2, a3, b0, b1);
                mma_bf16(acc[i][1], a0, a1, a2, a3, b2, b3);
            }
        }
        __syncthreads();   // protect smem before next tile overwrites
    }

    // Write partial O
    float* ob = g_O + (((size_t)b * MSPLIT + split) * Nn) * Dd;
#pragma unroll
    for (int i = 0; i < 6; i++) {
        const int r = 16 * i + g;
#pragma unroll
        for (int j = 0; j < 2; j++) {
            const int dloc = 16 * w + 8 * j + 2 * q;
            float* cf = acc[i][j];
            *(float2*)(ob + (size_t)r * Dd + dloc)       = make_float2(cf[0], cf[1]);
            *(float2*)(ob + (size_t)(r + 8) * Dd + dloc) = make_float2(cf[2], cf[3]);
        }
    }
}

// ---------------------------------------------------------------------------
// K3: out = q + sum_splits g_O
// ---------------------------------------------------------------------------
__global__ __launch_bounds__(256) void tlp_k3(const float* __restrict__ logits,
                                              float* __restrict__ out) {
    const size_t i4 = (size_t)blockIdx.x * 256 + threadIdx.x;
    const size_t nf4 = (size_t)Bb * Nn * Dd / 4;
    if (i4 >= nf4) return;
    const size_t b   = i4 / (Nn * Dd / 4);
    const size_t rem = i4 % (Nn * Dd / 4);

    float4 acc = ((const float4*)logits)[i4];
    const float4* po = (const float4*)g_O + (b * MSPLIT) * (Nn * Dd / 4) + rem;
#pragma unroll
    for (int s = 0; s < MSPLIT; s++) {
        float4 v = po[(size_t)s * (Nn * Dd / 4)];
        acc.x += v.x; acc.y += v.y; acc.z += v.z; acc.w += v.w;
    }
    ((float4*)out)[i4] = acc;
}

extern "C" void kernel_launch(void* const* d_in, const int* in_sizes, int n_in,
                              void* d_out, int out_size) {
    const float* logits = (const float*)d_in[0];
    const float* tl     = (const float*)d_in[1];
    float* out          = (float*)d_out;

    const int smem1 = (Nn * PB + MT * PB) * 2 + Nn * 4;                 // 61312 B
    const int smem2 = 128 * XP * 2 + 128 * PB * 2 + (Nn + 128) * 4;     // 62336 B

    cudaFuncSetAttribute(tlp_k1, cudaFuncAttributeMaxDynamicSharedMemorySize, smem1);
    cudaFuncSetAttribute(tlp_k2, cudaFuncAttributeMaxDynamicSharedMemorySize, smem2);

    tlp_k1<<<dim3(NTILES, Bb), 256, smem1>>>(logits, tl);
    tlp_k2<<<dim3(MSPLIT, Bb), 256, smem2>>>(tl);
    tlp_k3<<<(Bb * Nn * Dd / 4 + 255) / 256, 256>>>(logits, out);
}